// round 12
// baseline (speedup 1.0000x reference)
#include <cuda_runtime.h>

#define T_  512
#define I_  15
#define H_  64
#define B_  4096
#define RPD 3                 // batch rows per 2-warp domain
#define DOMS 2                // independent domains per block
#define THREADS 128
#define RPB (RPD * DOMS)      // 6 rows per block
#define NBLOCKS ((B_ + RPB - 1) / RPB)   // 683

typedef unsigned long long ull;

// named barrier over one 64-thread domain (ids 1,2; 0 is __syncthreads)
#define DBAR(dmid) asm volatile("bar.sync %0, 64;" :: "r"((dmid) + 1) : "memory")

// packed fp32x2 FMA (sm_100+): d.lo += a.lo*b.lo; d.hi += a.hi*b.hi
__device__ __forceinline__ void ffma2(ull &d, ull a, ull b) {
    asm("fma.rn.f32x2 %0, %1, %2, %0;" : "+l"(d) : "l"(a), "l"(b));
}
__device__ __forceinline__ ull pack2(float a, float b) {
    ull r; asm("mov.b64 %0, {%1, %2};" : "=l"(r) : "f"(a), "f"(b)); return r;
}
__device__ __forceinline__ float2 unpack2(ull v) {
    float2 f; asm("mov.b64 {%0, %1}, %2;" : "=f"(f.x), "=f"(f.y) : "l"(v)); return f;
}
// Accurate tanh, 2 MUFU: tanh(x) = (e-1)/(e+1), e = 2^(x*2*log2(e))
__device__ __forceinline__ float fast_tanh(float x) {
    float e; asm("ex2.approx.f32 %0, %1;" : "=f"(e) : "f"(x * 2.8853900817779268f));
    float r; asm("rcp.approx.f32 %0, %1;" : "=f"(r) : "f"(e + 1.0f));
    return (e - 1.0f) * r;
}

// Interleaved half layout inside one h row (64 floats):
//   h[kh*32 + q*4 + e] lives at float offset q*8 + kh*4 + e   (q=0..7)
// -> even lanes (kh=0) and odd lanes (kh=1) read 16B chunks in the SAME 128B
//    line, disjoint banks: 1 wavefront per LDS.128.
// x rows (16 floats, 15 real + pad): x[kh*8 + q*4 + e] at q*8 + kh*4 + e (q=0..1)

__global__ void __launch_bounds__(THREADS, 5) rnn_fused_kernel(
    const float* __restrict__ x,     // [B, T, I]
    const float* __restrict__ W_ih,  // [H, I]
    const float* __restrict__ W_hh,  // [H, H]
    const float* __restrict__ b_ih,  // [H]
    const float* __restrict__ b_hh,  // [H]
    const float* __restrict__ fc_w,  // [1, H]
    const float* __restrict__ fc_b,  // [1]
    float* __restrict__ out)         // [B, 1]
{
    __shared__ float hbuf[2][DOMS][RPD][H_];   // ping-pong h (interleaved)
    __shared__ float xbuf[2][DOMS][RPD][16];   // staged x_t (pos 15 = 0)
    __shared__ float red[DOMS][RPD][2];        // head partials per warp

    const int tid  = threadIdx.x;
    const int dm   = tid >> 6;       // domain 0: warps 0,1 / domain 1: warps 2,3
    const int dt   = tid & 63;       // thread id within domain
    const int jj   = dt >> 1;        // pair id = base output column 0..31
    const int kh   = dt & 1;         // k-half: 0 -> k[0,32), 1 -> k[32,64)
    const int lane = tid & 31;
    const int wd   = (tid >> 5) & 1; // warp within domain
    const int row0 = blockIdx.x * RPB + dm * RPD;

    const int j0 = jj, j1 = jj + 32; // this pair's two outputs

    // ---- Weights to registers ----
    ull whhA[16], whhB[16];          // W_hh rows j0/j1, this lane's k-half
    {
        const ull* w0 = (const ull*)(W_hh + j0 * H_ + kh * 32);
        const ull* w1 = (const ull*)(W_hh + j1 * H_ + kh * 32);
        #pragma unroll
        for (int i = 0; i < 16; ++i) { whhA[i] = w0[i]; whhB[i] = w1[i]; }
    }
    ull wihA[4], wihB[4];            // W_ih rows j0/j1, this lane's 8-input half
    #pragma unroll
    for (int q = 0; q < 2; ++q) {
        #pragma unroll
        for (int s = 0; s < 2; ++s) {
            int i0 = kh * 8 + q * 4 + 2 * s;
            float a0 = (i0     < I_) ? W_ih[j0 * I_ + i0]     : 0.0f;
            float b0 = (i0 + 1 < I_) ? W_ih[j0 * I_ + i0 + 1] : 0.0f;
            float a1 = (i0     < I_) ? W_ih[j1 * I_ + i0]     : 0.0f;
            float b1 = (i0 + 1 < I_) ? W_ih[j1 * I_ + i0 + 1] : 0.0f;
            wihA[2 * q + s] = pack2(a0, b0);
            wihB[2 * q + s] = pack2(a1, b1);
        }
    }

    const int  myj  = kh ? j1 : j0;          // the j this lane owns
    const float bias = b_ih[myj] + b_hh[myj];
    const float fcw  = fc_w[myj];
    const int hoff = (jj >> 2) * 8 + kh * 4 + (jj & 3);   // h[myj] slot in a row

    // ---- Init: h0 = 0, stage x(t=0), zero x pad ----
    #pragma unroll
    for (int i = 0; i < (2 * DOMS * RPD * H_ + THREADS - 1) / THREADS; ++i) {
        int idx = tid + i * THREADS;
        if (idx < 2 * DOMS * RPD * H_) ((float*)hbuf)[idx] = 0.0f;
    }
    const int  sr = dt / 15, si = dt % 15;     // staging lanes 0..44 per domain
    const bool stg = (dt < RPD * 15) && (row0 + sr < B_);
    const int  xoff = ((si & 7) >> 2) * 8 + (si >> 3) * 4 + (si & 3);
    const float* xp = x + ((long)(row0 + sr) * T_) * I_ + si;
    if (stg) xbuf[0][dm][sr][xoff] = *xp;
    if (dt < RPD) { xbuf[0][dm][dt][15] = 0.0f; xbuf[1][dm][dt][15] = 0.0f; }
    xp += I_;
    __syncthreads();

    // ---- Recurrence (domains independent; 2-warp named barrier) ----
    float hn[RPD];
    for (int t = 0; t < T_; ++t) {
        const int cur = t & 1, nxt = cur ^ 1;

        // prefetch x for t+1 (hidden behind this step's math)
        float xn = 0.0f;
        const bool pf = stg && (t + 1 < T_);
        if (pf) { xn = __ldg(xp); xp += I_; }

        // 16B chunk pointers for this lane's k-half
        const ulonglong2* hb2 = (const ulonglong2*)hbuf[cur][dm] + kh;
        const ulonglong2* xb2 = (const ulonglong2*)xbuf[cur][dm] + kh;

        ull acc0[RPD] = {0, 0, 0};
        ull acc1[RPD] = {0, 0, 0};

        // input projection: 2 chunks per row; each LDS feeds both outputs
        #pragma unroll
        for (int q = 0; q < 2; ++q) {
            #pragma unroll
            for (int r = 0; r < RPD; ++r) {
                ulonglong2 v = xb2[r * 4 + q * 2];
                ffma2(acc0[r], v.x, wihA[2 * q]);
                ffma2(acc0[r], v.y, wihA[2 * q + 1]);
                ffma2(acc1[r], v.x, wihB[2 * q]);
                ffma2(acc1[r], v.y, wihB[2 * q + 1]);
            }
        }
        // recurrent matvec: 8 chunks per row; 4 ffma2 per LDS.128
        #pragma unroll
        for (int q = 0; q < 8; ++q) {
            #pragma unroll
            for (int r = 0; r < RPD; ++r) {
                ulonglong2 v = hb2[r * 16 + q * 2];
                ffma2(acc0[r], v.x, whhA[2 * q]);
                ffma2(acc0[r], v.y, whhA[2 * q + 1]);
                ffma2(acc1[r], v.x, whhB[2 * q]);
                ffma2(acc1[r], v.y, whhB[2 * q + 1]);
            }
        }

        // combine k-halves: ONE shfl per row (send partner's j, keep mine)
        #pragma unroll
        for (int r = 0; r < RPD; ++r) {
            float2 f0 = unpack2(acc0[r]);     // partial for j0, my k-half
            float2 f1 = unpack2(acc1[r]);     // partial for j1, my k-half
            float s0 = f0.x + f0.y;
            float s1 = f1.x + f1.y;
            float s_mine  = kh ? s1 : s0;
            float s_other = kh ? s0 : s1;
            float tot = s_mine + __shfl_xor_sync(0xffffffffu, s_other, 1);
            hn[r] = fast_tanh(tot + bias);
            hbuf[nxt][dm][r][hoff] = hn[r];
        }
        if (pf) xbuf[nxt][dm][sr][xoff] = xn;
        DBAR(dm);   // couples only this domain's 2 warps
    }

    // ---- Head: out[row] = sum_j h_T[row][j] * fc_w[j] + fc_b ----
    float p[RPD];
    #pragma unroll
    for (int r = 0; r < RPD; ++r) {
        p[r] = hn[r] * fcw;
        #pragma unroll
        for (int o = 16; o > 0; o >>= 1)
            p[r] += __shfl_xor_sync(0xffffffffu, p[r], o);
    }
    if (lane == 0) {
        #pragma unroll
        for (int r = 0; r < RPD; ++r) red[dm][r][wd] = p[r];
    }
    DBAR(dm);
    if (dt < RPD && row0 + dt < B_)
        out[row0 + dt] = red[dm][dt][0] + red[dm][dt][1] + fc_b[0];
}

extern "C" void kernel_launch(void* const* d_in, const int* in_sizes, int n_in,
                              void* d_out, int out_size) {
    const float* x    = (const float*)d_in[0];
    const float* W_ih = (const float*)d_in[1];
    const float* W_hh = (const float*)d_in[2];
    const float* b_ih = (const float*)d_in[3];
    const float* b_hh = (const float*)d_in[4];
    const float* fc_w = (const float*)d_in[5];
    const float* fc_b = (const float*)d_in[6];
    rnn_fused_kernel<<<NBLOCKS, THREADS>>>(x, W_ih, W_hh, b_ih, b_hh,
                                           fc_w, fc_b, (float*)d_out);
}

// round 14
// speedup vs baseline: 1.0019x; 1.0019x over previous
#include <cuda_runtime.h>

#define T_  512
#define I_  15
#define H_  64
#define B_  4096
#define RPD 3                 // batch rows per 2-warp domain
#define DOMS 2                // independent domains per block
#define THREADS 128
#define RPB (RPD * DOMS)      // 6 rows per block
#define NBLOCKS ((B_ + RPB - 1) / RPB)   // 683

typedef unsigned long long ull;

// named barrier over one 64-thread domain (ids 1,2; 0 is __syncthreads)
#define DBAR(dmid) asm volatile("bar.sync %0, 64;" :: "r"((dmid) + 1) : "memory")

// packed fp32x2 FMA (sm_100+): d.lo += a.lo*b.lo; d.hi += a.hi*b.hi
__device__ __forceinline__ void ffma2(ull &d, ull a, ull b) {
    asm("fma.rn.f32x2 %0, %1, %2, %0;" : "+l"(d) : "l"(a), "l"(b));
}
__device__ __forceinline__ ull pack2(float a, float b) {
    ull r; asm("mov.b64 %0, {%1, %2};" : "=l"(r) : "f"(a), "f"(b)); return r;
}
__device__ __forceinline__ float2 unpack2(ull v) {
    float2 f; asm("mov.b64 {%0, %1}, %2;" : "=f"(f.x), "=f"(f.y) : "l"(v)); return f;
}
// Accurate tanh, 2 MUFU: tanh(x) = (e-1)/(e+1), e = 2^(x*2*log2(e))
__device__ __forceinline__ float fast_tanh(float x) {
    float e; asm("ex2.approx.f32 %0, %1;" : "=f"(e) : "f"(x * 2.8853900817779268f));
    float r; asm("rcp.approx.f32 %0, %1;" : "=f"(r) : "f"(e + 1.0f));
    return (e - 1.0f) * r;
}

// Interleaved half layout inside one h row (64 floats):
//   h[kh*32 + q*4 + e] lives at float offset q*8 + kh*4 + e   (q=0..7)
// -> even lanes (kh=0) and odd lanes (kh=1) read 16B chunks in the SAME 128B
//    line, disjoint banks: 1 wavefront per LDS.128.
// x rows (16 floats, 15 real + pad): x[kh*8 + q*4 + e] at q*8 + kh*4 + e (q=0..1)

__global__ void __launch_bounds__(THREADS, 5) rnn_fused_kernel(
    const float* __restrict__ x,     // [B, T, I]
    const float* __restrict__ W_ih,  // [H, I]
    const float* __restrict__ W_hh,  // [H, H]
    const float* __restrict__ b_ih,  // [H]
    const float* __restrict__ b_hh,  // [H]
    const float* __restrict__ fc_w,  // [1, H]
    const float* __restrict__ fc_b,  // [1]
    float* __restrict__ out)         // [B, 1]
{
    __shared__ float hbuf[2][DOMS][RPD][H_];   // ping-pong h (interleaved)
    __shared__ float xbuf[2][DOMS][RPD][16];   // staged x_t (pos 15 = 0)
    __shared__ float red[DOMS][RPD][2];        // head partials per warp

    const int tid  = threadIdx.x;
    const int dm   = tid >> 6;       // domain 0: warps 0,1 / domain 1: warps 2,3
    const int dt   = tid & 63;       // thread id within domain
    const int jj   = dt >> 1;        // pair id = base output column 0..31
    const int kh   = dt & 1;         // k-half: 0 -> k[0,32), 1 -> k[32,64)
    const int lane = tid & 31;
    const int wd   = (tid >> 5) & 1; // warp within domain
    const int row0 = blockIdx.x * RPB + dm * RPD;

    const int j0 = jj, j1 = jj + 32; // this pair's two outputs

    // ---- Weights to registers ----
    ull whhA[16], whhB[16];          // W_hh rows j0/j1, this lane's k-half
    {
        const ull* w0 = (const ull*)(W_hh + j0 * H_ + kh * 32);
        const ull* w1 = (const ull*)(W_hh + j1 * H_ + kh * 32);
        #pragma unroll
        for (int i = 0; i < 16; ++i) { whhA[i] = w0[i]; whhB[i] = w1[i]; }
    }
    ull wihA[4], wihB[4];            // W_ih rows j0/j1, this lane's 8-input half
    #pragma unroll
    for (int q = 0; q < 2; ++q) {
        #pragma unroll
        for (int s = 0; s < 2; ++s) {
            int i0 = kh * 8 + q * 4 + 2 * s;
            float a0 = (i0     < I_) ? W_ih[j0 * I_ + i0]     : 0.0f;
            float b0 = (i0 + 1 < I_) ? W_ih[j0 * I_ + i0 + 1] : 0.0f;
            float a1 = (i0     < I_) ? W_ih[j1 * I_ + i0]     : 0.0f;
            float b1 = (i0 + 1 < I_) ? W_ih[j1 * I_ + i0 + 1] : 0.0f;
            wihA[2 * q + s] = pack2(a0, b0);
            wihB[2 * q + s] = pack2(a1, b1);
        }
    }

    const int  myj  = kh ? j1 : j0;          // the j this lane owns
    const float bias = b_ih[myj] + b_hh[myj];
    const float fcw  = fc_w[myj];
    const int hoff = (jj >> 2) * 8 + kh * 4 + (jj & 3);   // h[myj] slot in a row

    // ---- Init: h0 = 0, stage x(t=0), zero x pad ----
    #pragma unroll
    for (int i = 0; i < (2 * DOMS * RPD * H_ + THREADS - 1) / THREADS; ++i) {
        int idx = tid + i * THREADS;
        if (idx < 2 * DOMS * RPD * H_) ((float*)hbuf)[idx] = 0.0f;
    }
    const int  sr = dt / 15, si = dt % 15;     // staging lanes 0..44 per domain
    const bool stg = (dt < RPD * 15) && (row0 + sr < B_);
    const int  xoff = ((si & 7) >> 2) * 8 + (si >> 3) * 4 + (si & 3);
    const float* xp = x + ((long)(row0 + sr) * T_) * I_ + si;
    if (stg) xbuf[0][dm][sr][xoff] = *xp;
    if (dt < RPD) { xbuf[0][dm][dt][15] = 0.0f; xbuf[1][dm][dt][15] = 0.0f; }
    xp += I_;
    __syncthreads();

    // ---- Recurrence (domains independent; 2-warp named barrier) ----
    float hn[RPD];
    for (int t = 0; t < T_; ++t) {
        const int cur = t & 1, nxt = cur ^ 1;

        // prefetch x for t+1 (hidden behind this step's math)
        float xn = 0.0f;
        const bool pf = stg && (t + 1 < T_);
        if (pf) { xn = __ldg(xp); xp += I_; }

        // 16B chunk pointers for this lane's k-half
        const ulonglong2* hb2 = (const ulonglong2*)hbuf[cur][dm] + kh;
        const ulonglong2* xb2 = (const ulonglong2*)xbuf[cur][dm] + kh;

        ull acc0[RPD] = {0, 0, 0};
        ull acc1[RPD] = {0, 0, 0};

        // input projection: 2 chunks per row; each LDS feeds both outputs
        #pragma unroll
        for (int q = 0; q < 2; ++q) {
            #pragma unroll
            for (int r = 0; r < RPD; ++r) {
                ulonglong2 v = xb2[r * 4 + q * 2];
                ffma2(acc0[r], v.x, wihA[2 * q]);
                ffma2(acc0[r], v.y, wihA[2 * q + 1]);
                ffma2(acc1[r], v.x, wihB[2 * q]);
                ffma2(acc1[r], v.y, wihB[2 * q + 1]);
            }
        }
        // recurrent matvec: 8 chunks per row; 4 ffma2 per LDS.128
        #pragma unroll
        for (int q = 0; q < 8; ++q) {
            #pragma unroll
            for (int r = 0; r < RPD; ++r) {
                ulonglong2 v = hb2[r * 16 + q * 2];
                ffma2(acc0[r], v.x, whhA[2 * q]);
                ffma2(acc0[r], v.y, whhA[2 * q + 1]);
                ffma2(acc1[r], v.x, whhB[2 * q]);
                ffma2(acc1[r], v.y, whhB[2 * q + 1]);
            }
        }

        // combine k-halves: ONE shfl per row (send partner's j, keep mine)
        #pragma unroll
        for (int r = 0; r < RPD; ++r) {
            float2 f0 = unpack2(acc0[r]);     // partial for j0, my k-half
            float2 f1 = unpack2(acc1[r]);     // partial for j1, my k-half
            float s0 = f0.x + f0.y;
            float s1 = f1.x + f1.y;
            float s_mine  = kh ? s1 : s0;
            float s_other = kh ? s0 : s1;
            float tot = s_mine + __shfl_xor_sync(0xffffffffu, s_other, 1);
            hn[r] = fast_tanh(tot + bias);
            hbuf[nxt][dm][r][hoff] = hn[r];
        }
        if (pf) xbuf[nxt][dm][sr][xoff] = xn;
        DBAR(dm);   // couples only this domain's 2 warps
    }

    // ---- Head: out[row] = sum_j h_T[row][j] * fc_w[j] + fc_b ----
    float p[RPD];
    #pragma unroll
    for (int r = 0; r < RPD; ++r) {
        p[r] = hn[r] * fcw;
        #pragma unroll
        for (int o = 16; o > 0; o >>= 1)
            p[r] += __shfl_xor_sync(0xffffffffu, p[r], o);
    }
    if (lane == 0) {
        #pragma unroll
        for (int r = 0; r < RPD; ++r) red[dm][r][wd] = p[r];
    }
    DBAR(dm);
    if (dt < RPD && row0 + dt < B_)
        out[row0 + dt] = red[dm][dt][0] + red[dm][dt][1] + fc_b[0];
}

extern "C" void kernel_launch(void* const* d_in, const int* in_sizes, int n_in,
                              void* d_out, int out_size) {
    const float* x    = (const float*)d_in[0];
    const float* W_ih = (const float*)d_in[1];
    const float* W_hh = (const float*)d_in[2];
    const float* b_ih = (const float*)d_in[3];
    const float* b_hh = (const float*)d_in[4];
    const float* fc_w = (const float*)d_in[5];
    const float* fc_b = (const float*)d_in[6];
    rnn_fused_kernel<<<NBLOCKS, THREADS>>>(x, W_ih, W_hh, b_ih, b_hh,
                                           fc_w, fc_b, (float*)d_out);
}

// round 15
// speedup vs baseline: 1.6939x; 1.6907x over previous
#include <cuda_runtime.h>

#define T_  512
#define I_  15
#define H_  64
#define B_  4096
#define THREADS 64            // one 2-warp domain per block
#define RPB 4                 // 4 rows per block: set A = {0,1}, set B = {2,3}
#define NBLOCKS (B_ / RPB)    // 1024

typedef unsigned long long ull;

// named barriers over the 64-thread block
#define BAR_A() asm volatile("bar.sync 1, 64;" ::: "memory")
#define BAR_B() asm volatile("bar.sync 2, 64;" ::: "memory")

// packed fp32x2 FMA (sm_100+): d.lo += a.lo*b.lo; d.hi += a.hi*b.hi
__device__ __forceinline__ void ffma2(ull &d, ull a, ull b) {
    asm("fma.rn.f32x2 %0, %1, %2, %0;" : "+l"(d) : "l"(a), "l"(b));
}
__device__ __forceinline__ ull pack2(float a, float b) {
    ull r; asm("mov.b64 %0, {%1, %2};" : "=l"(r) : "f"(a), "f"(b)); return r;
}
__device__ __forceinline__ float2 unpack2(ull v) {
    float2 f; asm("mov.b64 {%0, %1}, %2;" : "=f"(f.x), "=f"(f.y) : "l"(v)); return f;
}
// Accurate tanh, 2 MUFU: tanh(x) = (e-1)/(e+1), e = 2^(x*2*log2(e))
__device__ __forceinline__ float fast_tanh(float x) {
    float e; asm("ex2.approx.f32 %0, %1;" : "=f"(e) : "f"(x * 2.8853900817779268f));
    float r; asm("rcp.approx.f32 %0, %1;" : "=f"(r) : "f"(e + 1.0f));
    return (e - 1.0f) * r;
}

// Interleaved half layout inside one h row (64 floats):
//   h[kh*32 + q*4 + e] lives at float offset q*8 + kh*4 + e   (q=0..7)
// -> even lanes (kh=0) and odd lanes (kh=1) read 16B chunks in the SAME 128B
//    line, disjoint banks: 1 wavefront per LDS.128.
// x rows (16 floats, 15 real + pad): x[kh*8 + q*4 + e] at q*8 + kh*4 + e (q=0..1)

__global__ void __launch_bounds__(THREADS, 8) rnn_fused_kernel(
    const float* __restrict__ x,     // [B, T, I]
    const float* __restrict__ W_ih,  // [H, I]
    const float* __restrict__ W_hh,  // [H, H]
    const float* __restrict__ b_ih,  // [H]
    const float* __restrict__ b_hh,  // [H]
    const float* __restrict__ fc_w,  // [1, H]
    const float* __restrict__ fc_b,  // [1]
    float* __restrict__ out)         // [B, 1]
{
    __shared__ float hbuf[2][RPB][H_];   // ping-pong h (interleaved); rows 0,1=A 2,3=B
    __shared__ float xbuf[2][RPB][16];   // staged x_t (pos 15 = 0)
    __shared__ float red[RPB][2];        // head partials per warp

    const int tid  = threadIdx.x;
    const int jj   = tid >> 1;       // pair id = base output column 0..31
    const int kh   = tid & 1;        // k-half: 0 -> k[0,32), 1 -> k[32,64)
    const int lane = tid & 31;
    const int wrp  = tid >> 5;
    const int row0 = blockIdx.x * RPB;

    const int j0 = jj, j1 = jj + 32; // this pair's two outputs

    // ---- Weights to registers ----
    ull whhA[16], whhB[16];          // W_hh rows j0/j1, this lane's k-half
    {
        const ull* w0 = (const ull*)(W_hh + j0 * H_ + kh * 32);
        const ull* w1 = (const ull*)(W_hh + j1 * H_ + kh * 32);
        #pragma unroll
        for (int i = 0; i < 16; ++i) { whhA[i] = w0[i]; whhB[i] = w1[i]; }
    }
    ull wihA[4], wihB[4];            // W_ih rows j0/j1, this lane's 8-input half
    #pragma unroll
    for (int q = 0; q < 2; ++q) {
        #pragma unroll
        for (int s = 0; s < 2; ++s) {
            int i0 = kh * 8 + q * 4 + 2 * s;
            float a0 = (i0     < I_) ? W_ih[j0 * I_ + i0]     : 0.0f;
            float b0 = (i0 + 1 < I_) ? W_ih[j0 * I_ + i0 + 1] : 0.0f;
            float a1 = (i0     < I_) ? W_ih[j1 * I_ + i0]     : 0.0f;
            float b1 = (i0 + 1 < I_) ? W_ih[j1 * I_ + i0 + 1] : 0.0f;
            wihA[2 * q + s] = pack2(a0, b0);
            wihB[2 * q + s] = pack2(a1, b1);
        }
    }

    const int  myj  = kh ? j1 : j0;          // the j this lane owns
    const float bias = b_ih[myj] + b_hh[myj];
    const float fcw  = fc_w[myj];
    const int hoff = (jj >> 2) * 8 + kh * 4 + (jj & 3);   // h[myj] slot in a row

    // ---- Init: h0 = 0, stage x(t=0), zero x pad ----
    #pragma unroll
    for (int i = 0; i < (RPB * H_) / THREADS; ++i)
        ((float*)hbuf[0])[tid + i * THREADS] = 0.0f;
    const int  sr = tid / 15, si = tid % 15;     // staging lanes 0..59
    const bool stg = (tid < 60);
    const int  xoff = ((si & 7) >> 2) * 8 + (si >> 3) * 4 + (si & 3);
    const float* xp = x + ((long)(row0 + sr) * T_) * I_ + si;
    if (stg) xbuf[0][sr][xoff] = *xp;
    if (tid < RPB) { xbuf[0][tid][15] = 0.0f; xbuf[1][tid][15] = 0.0f; }
    xp += I_;
    __syncthreads();

    // ---- Recurrence, two pipelined rowsets (A = rows 0,1; B = rows 2,3) ----
    float hn[RPB];
    for (int t = 0; t < T_; ++t) {
        const int cur = t & 1, nxt = cur ^ 1;

        // prefetch x for t+1 (hidden behind this step's math)
        float xn = 0.0f;
        const bool pf = stg && (t + 1 < T_);
        if (pf) { xn = __ldg(xp); xp += I_; }

        const ulonglong2* hb2 = (const ulonglong2*)hbuf[cur] + kh;
        const ulonglong2* xb2 = (const ulonglong2*)xbuf[cur] + kh;

        ull acc0[RPB] = {0, 0, 0, 0};   // rows 0,1 = set A; rows 2,3 = set B
        ull acc1[RPB] = {0, 0, 0, 0};

        // ---- FMA burst, set A (rows 0,1) ----
        #pragma unroll
        for (int r = 0; r < 2; ++r) {
            #pragma unroll
            for (int q = 0; q < 2; ++q) {
                ulonglong2 v = xb2[r * 4 + q * 2];
                ffma2(acc0[r], v.x, wihA[2 * q]); ffma2(acc0[r], v.y, wihA[2 * q + 1]);
                ffma2(acc1[r], v.x, wihB[2 * q]); ffma2(acc1[r], v.y, wihB[2 * q + 1]);
            }
            #pragma unroll
            for (int q = 0; q < 8; ++q) {
                ulonglong2 v = hb2[r * 16 + q * 2];
                ffma2(acc0[r], v.x, whhA[2 * q]); ffma2(acc0[r], v.y, whhA[2 * q + 1]);
                ffma2(acc1[r], v.x, whhB[2 * q]); ffma2(acc1[r], v.y, whhB[2 * q + 1]);
            }
        }
        // ---- FMA burst, set B (rows 2,3) — covers A's tail latency ----
        #pragma unroll
        for (int r = 2; r < 4; ++r) {
            #pragma unroll
            for (int q = 0; q < 2; ++q) {
                ulonglong2 v = xb2[r * 4 + q * 2];
                ffma2(acc0[r], v.x, wihA[2 * q]); ffma2(acc0[r], v.y, wihA[2 * q + 1]);
                ffma2(acc1[r], v.x, wihB[2 * q]); ffma2(acc1[r], v.y, wihB[2 * q + 1]);
            }
            #pragma unroll
            for (int q = 0; q < 8; ++q) {
                ulonglong2 v = hb2[r * 16 + q * 2];
                ffma2(acc0[r], v.x, whhA[2 * q]); ffma2(acc0[r], v.y, whhA[2 * q + 1]);
                ffma2(acc1[r], v.x, whhB[2 * q]); ffma2(acc1[r], v.y, whhB[2 * q + 1]);
            }
        }

        // ---- finish A: combine halves, tanh, store; barrier A ----
        #pragma unroll
        for (int r = 0; r < 2; ++r) {
            float2 f0 = unpack2(acc0[r]);
            float2 f1 = unpack2(acc1[r]);
            float s0 = f0.x + f0.y, s1 = f1.x + f1.y;
            float s_mine  = kh ? s1 : s0;
            float s_other = kh ? s0 : s1;
            float tot = s_mine + __shfl_xor_sync(0xffffffffu, s_other, 1);
            hn[r] = fast_tanh(tot + bias);
            hbuf[nxt][r][hoff] = hn[r];
        }
        if (pf) xbuf[nxt][sr][xoff] = xn;   // x for both sets (before barA < barB)
        BAR_A();

        // ---- finish B; barrier B (wait covered by next step's FMA-A) ----
        #pragma unroll
        for (int r = 2; r < 4; ++r) {
            float2 f0 = unpack2(acc0[r]);
            float2 f1 = unpack2(acc1[r]);
            float s0 = f0.x + f0.y, s1 = f1.x + f1.y;
            float s_mine  = kh ? s1 : s0;
            float s_other = kh ? s0 : s1;
            float tot = s_mine + __shfl_xor_sync(0xffffffffu, s_other, 1);
            hn[r] = fast_tanh(tot + bias);
            hbuf[nxt][r][hoff] = hn[r];
        }
        BAR_B();
    }

    // ---- Head: out[row] = sum_j h_T[row][j] * fc_w[j] + fc_b ----
    float p[RPB];
    #pragma unroll
    for (int r = 0; r < RPB; ++r) {
        p[r] = hn[r] * fcw;
        #pragma unroll
        for (int o = 16; o > 0; o >>= 1)
            p[r] += __shfl_xor_sync(0xffffffffu, p[r], o);
    }
    if (lane == 0) {
        #pragma unroll
        for (int r = 0; r < RPB; ++r) red[r][wrp] = p[r];
    }
    __syncthreads();
    if (tid < RPB)
        out[row0 + tid] = red[tid][0] + red[tid][1] + fc_b[0];
}

extern "C" void kernel_launch(void* const* d_in, const int* in_sizes, int n_in,
                              void* d_out, int out_size) {
    const float* x    = (const float*)d_in[0];
    const float* W_ih = (const float*)d_in[1];
    const float* W_hh = (const float*)d_in[2];
    const float* b_ih = (const float*)d_in[3];
    const float* b_hh = (const float*)d_in[4];
    const float* fc_w = (const float*)d_in[5];
    const float* fc_b = (const float*)d_in[6];
    rnn_fused_kernel<<<NBLOCKS, THREADS>>>(x, W_ih, W_hh, b_ih, b_hh,
                                           fc_w, fc_b, (float*)d_out);
}